// round 7
// baseline (speedup 1.0000x reference)
#include <cuda_runtime.h>
#include <math.h>

#define B 512
#define D 256
#define HH 32
#define WW 32
#define TINV 10.0f  // 1/TEMPERATURE

// ---------------- scratch (no allocations allowed) ----------------
__device__ float g_d1[B * D];
__device__ float g_d2[B * D];
__device__ float g_nsqp[2][4][B];   // partial sum-of-squares per (which, z, b)
__device__ float g_p0[B * B];   // split-K partial 0 (raw dot products)
__device__ float g_p1[B * B];   // split-K partial 1
__device__ float g_sim[B * B];
__device__ float g_simT[B * B];
__device__ float g_n1[B];
__device__ float g_n2[B];
__device__ float g_rowmax[B];
__device__ float g_colmax[B];
__device__ float g_rowden[B];
__device__ float g_colden[B];

// ---------------- kernel 1: masked avg-pool descriptors (channel-split) ----------------
// grid (B, 2, 4), block 256 (8 warps). Block z handles channels [64z, 64z+64);
// warp w owns channels 64z + 8w .. +8. Lane = x pixel (predicated loads fetch
// only the ~2.2 sectors/row inside the x-mask; 8-deep MLP per warp).
__global__ void desc_kernel(const float* __restrict__ f1,
                            const float* __restrict__ f2,
                            const float* __restrict__ bb1,
                            const float* __restrict__ bb2) {
    const int b = blockIdx.x;
    const int which = blockIdx.y;
    const int z = blockIdx.z;
    const float* __restrict__ src = which ? f2 : f1;
    const float* __restrict__ box = which ? bb2 : bb1;
    float* __restrict__ gd = which ? g_d2 : g_d1;

    const int tid = threadIdx.x;
    const int lane = tid & 31;
    const int warp = tid >> 5;

    const float x0 = box[b * 4 + 0];
    const float y0 = box[b * 4 + 1];
    const float x1 = box[b * 4 + 2];
    const float y1 = box[b * 4 + 3];

    // x mask for this lane (exact reference fp ops: (i+0.5)/32)
    const float xc = ((float)lane + 0.5f) / 32.0f;
    const bool inx = (xc >= x0) && (xc <= x1);

    // y range (contiguous)
    int iy0 = 32, iy1 = -1;
#pragma unroll
    for (int y = 0; y < 32; y++) {
        float yc = ((float)y + 0.5f) / 32.0f;
        if (yc >= y0 && yc <= y1) { if (y < iy0) iy0 = y; iy1 = y; }
    }
    const int nx = __popc(__ballot_sync(0xffffffffu, inx));
    const int ny = (iy1 >= iy0) ? (iy1 - iy0 + 1) : 0;
    int cnt = nx * ny; if (cnt < 1) cnt = 1;
    const float inv_denom = 1.0f / (float)cnt;

    const int c0 = z * 64 + warp * 8;
    const float* p = src + (size_t)b * D * (HH * WW)
                         + (size_t)c0 * (HH * WW) + lane;

    float s0 = 0.f, s1 = 0.f, s2 = 0.f, s3 = 0.f;
    float s4 = 0.f, s5 = 0.f, s6 = 0.f, s7 = 0.f;
    for (int y = iy0; y <= iy1; y++) {
        const float* q = p + y * WW;
        if (inx) {
            s0 += q[0 * 1024]; s1 += q[1 * 1024];
            s2 += q[2 * 1024]; s3 += q[3 * 1024];
            s4 += q[4 * 1024]; s5 += q[5 * 1024];
            s6 += q[6 * 1024]; s7 += q[7 * 1024];
        }
    }
#pragma unroll
    for (int o = 16; o; o >>= 1) {
        s0 += __shfl_xor_sync(0xffffffffu, s0, o);
        s1 += __shfl_xor_sync(0xffffffffu, s1, o);
        s2 += __shfl_xor_sync(0xffffffffu, s2, o);
        s3 += __shfl_xor_sync(0xffffffffu, s3, o);
        s4 += __shfl_xor_sync(0xffffffffu, s4, o);
        s5 += __shfl_xor_sync(0xffffffffu, s5, o);
        s6 += __shfl_xor_sync(0xffffffffu, s6, o);
        s7 += __shfl_xor_sync(0xffffffffu, s7, o);
    }

    __shared__ float ssq[8];
    if (lane == 0) {
        const float v0 = s0 * inv_denom, v1 = s1 * inv_denom;
        const float v2 = s2 * inv_denom, v3 = s3 * inv_denom;
        const float v4 = s4 * inv_denom, v5 = s5 * inv_denom;
        const float v6 = s6 * inv_denom, v7 = s7 * inv_denom;
        float* o = gd + b * D + c0;
        o[0] = v0; o[1] = v1; o[2] = v2; o[3] = v3;
        o[4] = v4; o[5] = v5; o[6] = v6; o[7] = v7;
        ssq[warp] = v0 * v0 + v1 * v1 + v2 * v2 + v3 * v3
                  + v4 * v4 + v5 * v5 + v6 * v6 + v7 * v7;
    }
    __syncthreads();
    if (tid == 0) {
        float t = 0.f;
#pragma unroll
        for (int w = 0; w < 8; w++) t += ssq[w];
        g_nsqp[which][z][b] = t;
    }
}

// ---------------- kernel 2: split-K GEMM, raw partials ----------------
// grid (8, 8, 2), block 256. 64x64 tile, 4x4 microtile, K-half = 128 per z.
__global__ void simk_kernel() {
    __shared__ float As[64][68];
    __shared__ float Bs[64][68];

    const int tx = threadIdx.x & 15;
    const int ty = threadIdx.x >> 4;
    const int i0 = blockIdx.y * 64;
    const int j0 = blockIdx.x * 64;
    const int kt0 = blockIdx.z * 128;
    float* __restrict__ out = blockIdx.z ? g_p1 : g_p0;

    float acc[4][4];
#pragma unroll
    for (int r = 0; r < 4; r++)
#pragma unroll
        for (int c = 0; c < 4; c++) acc[r][c] = 0.f;

    for (int kt = kt0; kt < kt0 + 128; kt += 64) {
        for (int l = threadIdx.x; l < 64 * 64; l += 256) {
            const int kk = l & 63;
            const int row = l >> 6;
            As[kk][row] = g_d1[(i0 + row) * D + kt + kk];
            Bs[kk][row] = g_d2[(j0 + row) * D + kt + kk];
        }
        __syncthreads();
#pragma unroll 8
        for (int kk = 0; kk < 64; kk++) {
            float4 a = *(const float4*)&As[kk][ty * 4];
            float4 bv = *(const float4*)&Bs[kk][tx * 4];
            float av[4] = {a.x, a.y, a.z, a.w};
            float bw[4] = {bv.x, bv.y, bv.z, bv.w};
#pragma unroll
            for (int r = 0; r < 4; r++)
#pragma unroll
                for (int c = 0; c < 4; c++) acc[r][c] += av[r] * bw[c];
        }
        __syncthreads();
    }

#pragma unroll
    for (int r = 0; r < 4; r++)
#pragma unroll
        for (int c = 0; c < 4; c++)
            out[(i0 + ty * 4 + r) * B + j0 + tx * 4 + c] = acc[r][c];
}

// ---------------- kernel 3: combine partials + norms, write sim and simT ----------------
// grid (16, 16), block 256 (32x8). Prologue: threads 0-31 compute n1 for rows,
// 32-63 compute n2 for cols (sum 4 nsq partials + sqrt). Then 32x32 tile:
// read p0+p1 coalesced, write sim, transpose via smem, write simT. Also
// publishes g_n1/g_n2 once (blocks on the diagonal strip) for any later use.
__global__ void combineT_kernel() {
    __shared__ float t[32][33];
    __shared__ float sn1[32], sn2[32];
    const int tx = threadIdx.x & 31;
    const int ty = threadIdx.x >> 5;  // 0..7
    const int i0 = blockIdx.y * 32;
    const int j0 = blockIdx.x * 32;

    if (threadIdx.x < 32) {
        const int i = i0 + tx;
        const float nn = sqrtf(g_nsqp[0][0][i] + g_nsqp[0][1][i] +
                               g_nsqp[0][2][i] + g_nsqp[0][3][i]);
        sn1[tx] = nn;
        if (blockIdx.x == 0) g_n1[i] = nn;
    } else if (threadIdx.x < 64) {
        const int j = j0 + tx;
        const float nn = sqrtf(g_nsqp[1][0][j] + g_nsqp[1][1][j] +
                               g_nsqp[1][2][j] + g_nsqp[1][3][j]);
        sn2[tx] = nn;
        if (blockIdx.y == 0) g_n2[j] = nn;
    }
    __syncthreads();

    const float nj = sn2[tx];
#pragma unroll
    for (int r = 0; r < 4; r++) {
        const int i = i0 + ty + r * 8;
        const int idx = i * B + j0 + tx;
        const float s = (g_p0[idx] + g_p1[idx]) /
                        fmaxf(sn1[ty + r * 8] * nj, 1e-8f);
        g_sim[idx] = s;
        t[ty + r * 8][tx] = s;
    }
    __syncthreads();
#pragma unroll
    for (int r = 0; r < 4; r++) {
        const int j = j0 + ty + r * 8;
        g_simT[j * B + i0 + tx] = t[tx][ty + r * 8];
    }
}

// ---------------- kernel 4: maxes — pure row passes, 512-way parallel ----------------
// mode 0: colmax[i] = max(pos_i, max_{j!=i} sim[i,j]*T)   (row of sim)
// mode 1: rowmax[j] = max(pos_j, max_{i!=j} simT[j,i]*T)  (row of simT)
__global__ void max_kernel() {
    const int idx = blockIdx.x;
    const int mode = blockIdx.y;
    const int tid = threadIdx.x;
    const float* __restrict__ rowp = (mode ? g_simT : g_sim) + idx * B;
    float m = -INFINITY;
#pragma unroll
    for (int k = 0; k < 2; k++) {
        const int j = tid + k * 256;
        if (j != idx) m = fmaxf(m, rowp[j] * TINV);
    }
    __shared__ float sm[256];
    sm[tid] = m;
    __syncthreads();
    for (int s = 128; s; s >>= 1) {
        if (tid < s) sm[tid] = fmaxf(sm[tid], sm[tid + s]);
        __syncthreads();
    }
    if (tid == 0) {
        const float pos = rowp[idx] * TINV;
        const float mm = fmaxf(pos, sm[0]);
        if (mode == 0) g_colmax[idx] = mm; else g_rowmax[idx] = mm;
    }
}

// ---------------- kernel 5: denominators — pure row passes ----------------
// mode 0: row_den[i] = sum_{j!=i} exp(sim[i,j]*T - rowmax[j]) + exp(pos_i - rowmax[i])
// mode 1: col_den[j] = sum_{i!=j} exp(simT[j,i]*T - colmax[j]) + exp(pos_j - colmax[j])
__global__ void den_kernel() {
    const int idx = blockIdx.x;
    const int mode = blockIdx.y;
    const int tid = threadIdx.x;
    const float* __restrict__ rowp = (mode ? g_simT : g_sim) + idx * B;
    float s = 0.f;
    if (mode == 0) {
#pragma unroll
        for (int k = 0; k < 2; k++) {
            const int j = tid + k * 256;
            if (j != idx) s += expf(rowp[j] * TINV - g_rowmax[j]);
        }
    } else {
        const float cm = g_colmax[idx];
#pragma unroll
        for (int k = 0; k < 2; k++) {
            const int i = tid + k * 256;
            if (i != idx) s += expf(rowp[i] * TINV - cm);
        }
    }
    __shared__ float sm[256];
    sm[tid] = s;
    __syncthreads();
    for (int st = 128; st; st >>= 1) {
        if (tid < st) sm[tid] += sm[tid + st];
        __syncthreads();
    }
    if (tid == 0) {
        const float pos = rowp[idx] * TINV;
        if (mode == 0) g_rowden[idx] = sm[0] + expf(pos - g_rowmax[idx]);
        else           g_colden[idx] = sm[0] + expf(pos - g_colmax[idx]);
    }
}

// ---------------- kernel 6: final loss ----------------
__global__ void loss_kernel(float* __restrict__ out) {
    const int tid = threadIdx.x;  // 512 threads
    __shared__ float sm[B];
    const float pos = g_sim[tid * B + tid] * TINV;
    const float rlog = logf(expf(pos - g_rowmax[tid]) / g_rowden[tid] + 1e-20f);
    const float clog = logf(expf(pos - g_colmax[tid]) / g_colden[tid] + 1e-20f);
    sm[tid] = -rlog - clog;
    __syncthreads();
    for (int s = 256; s; s >>= 1) {
        if (tid < s) sm[tid] += sm[tid + s];
        __syncthreads();
    }
    if (tid == 0) out[0] = sm[0] / (2.0f * (float)B);
}

extern "C" void kernel_launch(void* const* d_in, const int* in_sizes, int n_in,
                              void* d_out, int out_size) {
    const float* f1 = (const float*)d_in[0];
    const float* f2 = (const float*)d_in[1];
    const float* bb1 = (const float*)d_in[2];
    const float* bb2 = (const float*)d_in[3];
    float* out = (float*)d_out;

    desc_kernel<<<dim3(B, 2, 4), 256>>>(f1, f2, bb1, bb2);
    simk_kernel<<<dim3(8, 8, 2), 256>>>();
    combineT_kernel<<<dim3(16, 16), 256>>>();
    max_kernel<<<dim3(B, 2), 256>>>();
    den_kernel<<<dim3(B, 2), 256>>>();
    loss_kernel<<<1, B>>>(out);
}

// round 8
// speedup vs baseline: 1.3650x; 1.3650x over previous
#include <cuda_runtime.h>
#include <math.h>

#define B 512
#define D 256
#define HH 32
#define WW 32
#define TINV 10.0f  // 1/TEMPERATURE

// ---------------- scratch (no allocations allowed) ----------------
__device__ float g_d1[B * D];
__device__ float g_d2[B * D];
__device__ float g_n1[B];
__device__ float g_n2[B];
__device__ float g_p0[B * B];   // split-K partial 0 (raw dot products)
__device__ float g_p1[B * B];   // split-K partial 1
__device__ float g_sim[B * B];
__device__ float g_simT[B * B];
__device__ float g_rowmax[B];
__device__ float g_colmax[B];
__device__ float g_rowden[B];
__device__ float g_colden[B];

// ---------------- kernel 1: masked avg-pool descriptors + norms ----------------
// grid (B, 2), block 256 (8 warps). Warp w owns channels [32w, 32w+32) in two
// 16-channel groups. Lane packing: half = lane>>4 selects one of 2 channels per
// accumulator slot; pixel = ix0 + (lane&15) where ix0 is the first masked x
// (mask is contiguous, nx <= 13 < 16 always fits). Loads predicated on the
// exact mask, so sector traffic equals the lane-per-pixel layout while using
// half the LDG instructions.
__global__ void desc_kernel(const float* __restrict__ f1,
                            const float* __restrict__ f2,
                            const float* __restrict__ bb1,
                            const float* __restrict__ bb2) {
    const int b = blockIdx.x;
    const int which = blockIdx.y;
    const float* __restrict__ src = which ? f2 : f1;
    const float* __restrict__ box = which ? bb2 : bb1;
    float* __restrict__ gd = which ? g_d2 : g_d1;
    float* __restrict__ gn = which ? g_n2 : g_n1;

    const int tid = threadIdx.x;
    const int lane = tid & 31;
    const int warp = tid >> 5;
    const int half = lane >> 4;   // 0,1 -> channel offset 0 or 8
    const int sub = lane & 15;    // pixel slot within the mask window

    const float x0 = box[b * 4 + 0];
    const float y0 = box[b * 4 + 1];
    const float x1 = box[b * 4 + 2];
    const float y1 = box[b * 4 + 3];

    // full x-mask via ballot over lane-as-pixel (exact reference fp ops)
    const float xc_l = ((float)lane + 0.5f) / 32.0f;
    const bool inx_l = (xc_l >= x0) && (xc_l <= x1);
    const unsigned xm = __ballot_sync(0xffffffffu, inx_l);
    const int nx = __popc(xm);
    const int ix0 = xm ? (__ffs(xm) - 1) : 0;

    // y range (contiguous)
    int iy0 = 32, iy1 = -1;
#pragma unroll
    for (int y = 0; y < 32; y++) {
        float yc = ((float)y + 0.5f) / 32.0f;
        if (yc >= y0 && yc <= y1) { if (y < iy0) iy0 = y; iy1 = y; }
    }
    const int ny = (iy1 >= iy0) ? (iy1 - iy0 + 1) : 0;
    int cnt = nx * ny; if (cnt < 1) cnt = 1;
    const float inv_denom = 1.0f / (float)cnt;

    // this lane's pixel + exact-mask predicate
    const int px = ix0 + sub;
    bool inm = false;
    if (px < 32) {
        const float xc = ((float)px + 0.5f) / 32.0f;
        inm = (xc >= x0) && (xc <= x1);
    }

    __shared__ float sdesc[D];
    __shared__ float sred[256];

    const float* base = src + (size_t)b * D * (HH * WW);

    // two groups of 16 channels per warp; acc g -> channel c0 + g (this half)
    for (int dd = 0; dd < 32; dd += 16) {
        const int c0 = (warp << 5) + dd + half * 8;
        const float* p = base + (size_t)c0 * (HH * WW) + px;
        float s0 = 0.f, s1 = 0.f, s2 = 0.f, s3 = 0.f;
        float s4 = 0.f, s5 = 0.f, s6 = 0.f, s7 = 0.f;
        for (int y = iy0; y <= iy1; y++) {
            const float* q = p + y * WW;
            if (inm) {
                s0 += q[0 * 1024]; s1 += q[1 * 1024];
                s2 += q[2 * 1024]; s3 += q[3 * 1024];
                s4 += q[4 * 1024]; s5 += q[5 * 1024];
                s6 += q[6 * 1024]; s7 += q[7 * 1024];
            }
        }
        // reduce within each 16-lane half (xor 8,4,2,1 stays inside the half)
#pragma unroll
        for (int o = 8; o; o >>= 1) {
            s0 += __shfl_xor_sync(0xffffffffu, s0, o);
            s1 += __shfl_xor_sync(0xffffffffu, s1, o);
            s2 += __shfl_xor_sync(0xffffffffu, s2, o);
            s3 += __shfl_xor_sync(0xffffffffu, s3, o);
            s4 += __shfl_xor_sync(0xffffffffu, s4, o);
            s5 += __shfl_xor_sync(0xffffffffu, s5, o);
            s6 += __shfl_xor_sync(0xffffffffu, s6, o);
            s7 += __shfl_xor_sync(0xffffffffu, s7, o);
        }
        if (sub == 0) {  // lanes 0 and 16 hold their half's totals
            sdesc[c0 + 0] = s0 * inv_denom;
            sdesc[c0 + 1] = s1 * inv_denom;
            sdesc[c0 + 2] = s2 * inv_denom;
            sdesc[c0 + 3] = s3 * inv_denom;
            sdesc[c0 + 4] = s4 * inv_denom;
            sdesc[c0 + 5] = s5 * inv_denom;
            sdesc[c0 + 6] = s6 * inv_denom;
            sdesc[c0 + 7] = s7 * inv_denom;
        }
    }
    __syncthreads();

    const float v = sdesc[tid];
    gd[b * D + tid] = v;

    sred[tid] = v * v;
    __syncthreads();
    for (int s = 128; s; s >>= 1) {
        if (tid < s) sred[tid] += sred[tid + s];
        __syncthreads();
    }
    if (tid == 0) gn[b] = sqrtf(sred[0]);
}

// ---------------- kernel 2: split-K GEMM, raw partials ----------------
// grid (8, 8, 2), block 256. 64x64 tile, 4x4 microtile, K-half = 128 per z.
__global__ void simk_kernel() {
    __shared__ float As[64][68];
    __shared__ float Bs[64][68];

    const int tx = threadIdx.x & 15;
    const int ty = threadIdx.x >> 4;
    const int i0 = blockIdx.y * 64;
    const int j0 = blockIdx.x * 64;
    const int kt0 = blockIdx.z * 128;
    float* __restrict__ out = blockIdx.z ? g_p1 : g_p0;

    float acc[4][4];
#pragma unroll
    for (int r = 0; r < 4; r++)
#pragma unroll
        for (int c = 0; c < 4; c++) acc[r][c] = 0.f;

    for (int kt = kt0; kt < kt0 + 128; kt += 64) {
        for (int l = threadIdx.x; l < 64 * 64; l += 256) {
            const int kk = l & 63;
            const int row = l >> 6;
            As[kk][row] = g_d1[(i0 + row) * D + kt + kk];
            Bs[kk][row] = g_d2[(j0 + row) * D + kt + kk];
        }
        __syncthreads();
#pragma unroll 8
        for (int kk = 0; kk < 64; kk++) {
            float4 a = *(const float4*)&As[kk][ty * 4];
            float4 bv = *(const float4*)&Bs[kk][tx * 4];
            float av[4] = {a.x, a.y, a.z, a.w};
            float bw[4] = {bv.x, bv.y, bv.z, bv.w};
#pragma unroll
            for (int r = 0; r < 4; r++)
#pragma unroll
                for (int c = 0; c < 4; c++) acc[r][c] += av[r] * bw[c];
        }
        __syncthreads();
    }

#pragma unroll
    for (int r = 0; r < 4; r++)
#pragma unroll
        for (int c = 0; c < 4; c++)
            out[(i0 + ty * 4 + r) * B + j0 + tx * 4 + c] = acc[r][c];
}

// ---------------- kernel 3: combine partials + norms, write sim and simT ----------------
// grid (16, 16), block 256 (32x8). Each block handles a 32x32 tile:
// reads p0+p1 coalesced, writes sim coalesced, transposes via smem,
// writes simT coalesced. Everything stays in L2.
__global__ void combineT_kernel() {
    __shared__ float t[32][33];
    const int tx = threadIdx.x & 31;
    const int ty = threadIdx.x >> 5;  // 0..7
    const int i0 = blockIdx.y * 32;
    const int j0 = blockIdx.x * 32;

    const float nj = g_n2[j0 + tx];
#pragma unroll
    for (int r = 0; r < 4; r++) {
        const int i = i0 + ty + r * 8;
        const int idx = i * B + j0 + tx;
        const float s = (g_p0[idx] + g_p1[idx]) /
                        fmaxf(g_n1[i] * nj, 1e-8f);
        g_sim[idx] = s;
        t[ty + r * 8][tx] = s;
    }
    __syncthreads();
#pragma unroll
    for (int r = 0; r < 4; r++) {
        const int j = j0 + ty + r * 8;
        g_simT[j * B + i0 + tx] = t[tx][ty + r * 8];
    }
}

// ---------------- kernel 4: maxes — pure row passes, 512-way parallel ----------------
// mode 0: colmax[i] = max(pos_i, max_{j!=i} sim[i,j]*T)   (row of sim)
// mode 1: rowmax[j] = max(pos_j, max_{i!=j} simT[j,i]*T)  (row of simT)
__global__ void max_kernel() {
    const int idx = blockIdx.x;
    const int mode = blockIdx.y;
    const int tid = threadIdx.x;
    const float* __restrict__ rowp = (mode ? g_simT : g_sim) + idx * B;
    float m = -INFINITY;
#pragma unroll
    for (int k = 0; k < 2; k++) {
        const int j = tid + k * 256;
        if (j != idx) m = fmaxf(m, rowp[j] * TINV);
    }
    __shared__ float sm[256];
    sm[tid] = m;
    __syncthreads();
    for (int s = 128; s; s >>= 1) {
        if (tid < s) sm[tid] = fmaxf(sm[tid], sm[tid + s]);
        __syncthreads();
    }
    if (tid == 0) {
        const float pos = rowp[idx] * TINV;
        const float mm = fmaxf(pos, sm[0]);
        if (mode == 0) g_colmax[idx] = mm; else g_rowmax[idx] = mm;
    }
}

// ---------------- kernel 5: denominators — pure row passes ----------------
// mode 0: row_den[i] = sum_{j!=i} exp(sim[i,j]*T - rowmax[j]) + exp(pos_i - rowmax[i])
// mode 1: col_den[j] = sum_{i!=j} exp(simT[j,i]*T - colmax[j]) + exp(pos_j - colmax[j])
__global__ void den_kernel() {
    const int idx = blockIdx.x;
    const int mode = blockIdx.y;
    const int tid = threadIdx.x;
    const float* __restrict__ rowp = (mode ? g_simT : g_sim) + idx * B;
    float s = 0.f;
    if (mode == 0) {
#pragma unroll
        for (int k = 0; k < 2; k++) {
            const int j = tid + k * 256;
            if (j != idx) s += expf(rowp[j] * TINV - g_rowmax[j]);
        }
    } else {
        const float cm = g_colmax[idx];
#pragma unroll
        for (int k = 0; k < 2; k++) {
            const int i = tid + k * 256;
            if (i != idx) s += expf(rowp[i] * TINV - cm);
        }
    }
    __shared__ float sm[256];
    sm[tid] = s;
    __syncthreads();
    for (int st = 128; st; st >>= 1) {
        if (tid < st) sm[tid] += sm[tid + st];
        __syncthreads();
    }
    if (tid == 0) {
        const float pos = rowp[idx] * TINV;
        if (mode == 0) g_rowden[idx] = sm[0] + expf(pos - g_rowmax[idx]);
        else           g_colden[idx] = sm[0] + expf(pos - g_colmax[idx]);
    }
}

// ---------------- kernel 6: final loss ----------------
__global__ void loss_kernel(float* __restrict__ out) {
    const int tid = threadIdx.x;  // 512 threads
    __shared__ float sm[B];
    const float pos = g_sim[tid * B + tid] * TINV;
    const float rlog = logf(expf(pos - g_rowmax[tid]) / g_rowden[tid] + 1e-20f);
    const float clog = logf(expf(pos - g_colmax[tid]) / g_colden[tid] + 1e-20f);
    sm[tid] = -rlog - clog;
    __syncthreads();
    for (int s = 256; s; s >>= 1) {
        if (tid < s) sm[tid] += sm[tid + s];
        __syncthreads();
    }
    if (tid == 0) out[0] = sm[0] / (2.0f * (float)B);
}

extern "C" void kernel_launch(void* const* d_in, const int* in_sizes, int n_in,
                              void* d_out, int out_size) {
    const float* f1 = (const float*)d_in[0];
    const float* f2 = (const float*)d_in[1];
    const float* bb1 = (const float*)d_in[2];
    const float* bb2 = (const float*)d_in[3];
    float* out = (float*)d_out;

    desc_kernel<<<dim3(B, 2), 256>>>(f1, f2, bb1, bb2);
    simk_kernel<<<dim3(8, 8, 2), 256>>>();
    combineT_kernel<<<dim3(16, 16), 256>>>();
    max_kernel<<<dim3(B, 2), 256>>>();
    den_kernel<<<dim3(B, 2), 256>>>();
    loss_kernel<<<1, B>>>(out);
}

// round 12
// speedup vs baseline: 1.3699x; 1.0036x over previous
#include <cuda_runtime.h>
#include <math.h>

#define B 512
#define D 256
#define HH 32
#define WW 32
#define TINV 10.0f  // 1/TEMPERATURE

// ---------------- scratch (no allocations allowed) ----------------
__device__ float g_d1[B * D];
__device__ float g_d2[B * D];
__device__ float g_n1[B];
__device__ float g_n2[B];
__device__ float g_p0[B * B];   // split-K partial 0 (raw dot products)
__device__ float g_p1[B * B];   // split-K partial 1
__device__ float g_sim[B * B];
__device__ float g_simT[B * B];
__device__ unsigned g_rowmax_u[B];  // order-preserving uint enc; reset by loss_kernel
__device__ unsigned g_colmax_u[B];
__device__ float g_rowden[B];
__device__ float g_colden[B];

// order-preserving float<->uint encoding (atomicMax-able)
__device__ __forceinline__ unsigned encf(float f) {
    unsigned u = __float_as_uint(f);
    return (u & 0x80000000u) ? ~u : (u | 0x80000000u);
}
__device__ __forceinline__ float decf(unsigned u) {
    return __uint_as_float((u & 0x80000000u) ? (u & 0x7FFFFFFFu) : ~u);
}

// ---------------- kernel 1: masked avg-pool descriptors + norms ----------------
// grid (B, 2), block 512 (16 warps). Warp w owns channels [16w, 16w+16) in ONE
// group (no sequential outer loop -> half the per-block critical path of R7).
// Lane packing: half = lane>>4 selects channel offset 0/8; pixel = ix0+(lane&15)
// where ix0 is the first masked x (mask contiguous, nx <= 13 < 16). Loads are
// predicated on the exact mask -> sector traffic identical to lane-per-pixel.
__global__ void desc_kernel(const float* __restrict__ f1,
                            const float* __restrict__ f2,
                            const float* __restrict__ bb1,
                            const float* __restrict__ bb2) {
    const int b = blockIdx.x;
    const int which = blockIdx.y;
    const float* __restrict__ src = which ? f2 : f1;
    const float* __restrict__ box = which ? bb2 : bb1;
    float* __restrict__ gd = which ? g_d2 : g_d1;
    float* __restrict__ gn = which ? g_n2 : g_n1;

    const int tid = threadIdx.x;
    const int lane = tid & 31;
    const int warp = tid >> 5;       // 0..15
    const int half = lane >> 4;      // 0,1 -> channel offset 0 or 8
    const int sub = lane & 15;       // pixel slot within the mask window

    const float x0 = box[b * 4 + 0];
    const float y0 = box[b * 4 + 1];
    const float x1 = box[b * 4 + 2];
    const float y1 = box[b * 4 + 3];

    // full x-mask via ballot over lane-as-pixel (exact reference fp ops)
    const float xc_l = ((float)lane + 0.5f) / 32.0f;
    const bool inx_l = (xc_l >= x0) && (xc_l <= x1);
    const unsigned xm = __ballot_sync(0xffffffffu, inx_l);
    const int nx = __popc(xm);
    const int ix0 = xm ? (__ffs(xm) - 1) : 0;

    // y range (contiguous)
    int iy0 = 32, iy1 = -1;
#pragma unroll
    for (int y = 0; y < 32; y++) {
        float yc = ((float)y + 0.5f) / 32.0f;
        if (yc >= y0 && yc <= y1) { if (y < iy0) iy0 = y; iy1 = y; }
    }
    const int ny = (iy1 >= iy0) ? (iy1 - iy0 + 1) : 0;
    int cnt = nx * ny; if (cnt < 1) cnt = 1;
    const float inv_denom = 1.0f / (float)cnt;

    // this lane's pixel + exact-mask predicate
    const int px = ix0 + sub;
    bool inm = false;
    if (px < 32) {
        const float xc = ((float)px + 0.5f) / 32.0f;
        inm = (xc >= x0) && (xc <= x1);
    }

    __shared__ float sdesc[D];
    __shared__ float sred[256];

    const int c0 = (warp << 4) + half * 8;
    const float* p = src + (size_t)b * D * (HH * WW)
                         + (size_t)c0 * (HH * WW) + px;

    float s0 = 0.f, s1 = 0.f, s2 = 0.f, s3 = 0.f;
    float s4 = 0.f, s5 = 0.f, s6 = 0.f, s7 = 0.f;
    for (int y = iy0; y <= iy1; y++) {
        const float* q = p + y * WW;
        if (inm) {
            s0 += q[0 * 1024]; s1 += q[1 * 1024];
            s2 += q[2 * 1024]; s3 += q[3 * 1024];
            s4 += q[4 * 1024]; s5 += q[5 * 1024];
            s6 += q[6 * 1024]; s7 += q[7 * 1024];
        }
    }
    // reduce within each 16-lane half
#pragma unroll
    for (int o = 8; o; o >>= 1) {
        s0 += __shfl_xor_sync(0xffffffffu, s0, o);
        s1 += __shfl_xor_sync(0xffffffffu, s1, o);
        s2 += __shfl_xor_sync(0xffffffffu, s2, o);
        s3 += __shfl_xor_sync(0xffffffffu, s3, o);
        s4 += __shfl_xor_sync(0xffffffffu, s4, o);
        s5 += __shfl_xor_sync(0xffffffffu, s5, o);
        s6 += __shfl_xor_sync(0xffffffffu, s6, o);
        s7 += __shfl_xor_sync(0xffffffffu, s7, o);
    }
    if (sub == 0) {  // lanes 0 and 16 hold their half's totals
        sdesc[c0 + 0] = s0 * inv_denom;
        sdesc[c0 + 1] = s1 * inv_denom;
        sdesc[c0 + 2] = s2 * inv_denom;
        sdesc[c0 + 3] = s3 * inv_denom;
        sdesc[c0 + 4] = s4 * inv_denom;
        sdesc[c0 + 5] = s5 * inv_denom;
        sdesc[c0 + 6] = s6 * inv_denom;
        sdesc[c0 + 7] = s7 * inv_denom;
    }
    __syncthreads();

    if (tid < 256) {
        const float v = sdesc[tid];
        gd[b * D + tid] = v;
        sred[tid] = v * v;
    }
    __syncthreads();
    for (int s = 128; s; s >>= 1) {
        if (tid < s) sred[tid] += sred[tid + s];
        __syncthreads();
    }
    if (tid == 0) gn[b] = sqrtf(sred[0]);
}

// ---------------- kernel 2: split-K GEMM, raw partials ----------------
// grid (8, 8, 2), block 256. 64x64 tile, 4x4 microtile, K-half = 128 per z.
__global__ void simk_kernel() {
    __shared__ float As[64][68];
    __shared__ float Bs[64][68];

    const int tx = threadIdx.x & 15;
    const int ty = threadIdx.x >> 4;
    const int i0 = blockIdx.y * 64;
    const int j0 = blockIdx.x * 64;
    const int kt0 = blockIdx.z * 128;
    float* __restrict__ out = blockIdx.z ? g_p1 : g_p0;

    float acc[4][4];
#pragma unroll
    for (int r = 0; r < 4; r++)
#pragma unroll
        for (int c = 0; c < 4; c++) acc[r][c] = 0.f;

    for (int kt = kt0; kt < kt0 + 128; kt += 64) {
        for (int l = threadIdx.x; l < 64 * 64; l += 256) {
            const int kk = l & 63;
            const int row = l >> 6;
            As[kk][row] = g_d1[(i0 + row) * D + kt + kk];
            Bs[kk][row] = g_d2[(j0 + row) * D + kt + kk];
        }
        __syncthreads();
#pragma unroll 8
        for (int kk = 0; kk < 64; kk++) {
            float4 a = *(const float4*)&As[kk][ty * 4];
            float4 bv = *(const float4*)&Bs[kk][tx * 4];
            float av[4] = {a.x, a.y, a.z, a.w};
            float bw[4] = {bv.x, bv.y, bv.z, bv.w};
#pragma unroll
            for (int r = 0; r < 4; r++)
#pragma unroll
                for (int c = 0; c < 4; c++) acc[r][c] += av[r] * bw[c];
        }
        __syncthreads();
    }

#pragma unroll
    for (int r = 0; r < 4; r++)
#pragma unroll
        for (int c = 0; c < 4; c++)
            out[(i0 + ty * 4 + r) * B + j0 + tx * 4 + c] = acc[r][c];
}

// ---------------- kernel 3: combine + transpose + BOTH maxes ----------------
// grid (16, 16), block 256 (32x8). 32x32 tile: read p0+p1 coalesced, write sim
// + simT (via smem transpose). Fused maxes (diagonal included — equivalent to
// reference's max(pos, neg.max)):
//   colmax[i] = max_j sim[i,j]*T  -> row-reduce, atomicMax
//   rowmax[j] = max_i sim[i,j]*T  -> reduce on transposed tile, atomicMax
__global__ void combineT_kernel() {
    __shared__ float t[32][33];
    const int tx = threadIdx.x & 31;
    const int ty = threadIdx.x >> 5;  // 0..7
    const int i0 = blockIdx.y * 32;
    const int j0 = blockIdx.x * 32;

    const float nj = g_n2[j0 + tx];
#pragma unroll
    for (int r = 0; r < 4; r++) {
        const int i = i0 + ty + r * 8;
        const int idx = i * B + j0 + tx;
        const float s = (g_p0[idx] + g_p1[idx]) /
                        fmaxf(g_n1[i] * nj, 1e-8f);
        g_sim[idx] = s;
        t[ty + r * 8][tx] = s;
        // row max over the tile (32 lanes = full tile row)
        float m = s;
#pragma unroll
        for (int o = 16; o; o >>= 1)
            m = fmaxf(m, __shfl_xor_sync(0xffffffffu, m, o));
        if (tx == 0) atomicMax(&g_colmax_u[i], encf(m * TINV));
    }
    __syncthreads();
#pragma unroll
    for (int r = 0; r < 4; r++) {
        const int j = j0 + ty + r * 8;
        const float s = t[tx][ty + r * 8];
        g_simT[j * B + i0 + tx] = s;
        float m = s;
#pragma unroll
        for (int o = 16; o; o >>= 1)
            m = fmaxf(m, __shfl_xor_sync(0xffffffffu, m, o));
        if (tx == 0) atomicMax(&g_rowmax_u[j], encf(m * TINV));
    }
}

// ---------------- kernel 4: denominators — pure row passes ----------------
// mode 0: row_den[i] = sum_{j!=i} exp(sim[i,j]*T - rowmax[j]) + exp(pos_i - rowmax[i])
// mode 1: col_den[j] = sum_{i!=j} exp(simT[j,i]*T - colmax[j]) + exp(pos_j - colmax[j])
__global__ void den_kernel() {
    const int idx = blockIdx.x;
    const int mode = blockIdx.y;
    const int tid = threadIdx.x;
    const float* __restrict__ rowp = (mode ? g_simT : g_sim) + idx * B;
    float s = 0.f;
    if (mode == 0) {
#pragma unroll
        for (int k = 0; k < 2; k++) {
            const int j = tid + k * 256;
            if (j != idx) s += expf(rowp[j] * TINV - decf(g_rowmax_u[j]));
        }
    } else {
        const float cm = decf(g_colmax_u[idx]);
#pragma unroll
        for (int k = 0; k < 2; k++) {
            const int i = tid + k * 256;
            if (i != idx) s += expf(rowp[i] * TINV - cm);
        }
    }
    __shared__ float sm[256];
    sm[tid] = s;
    __syncthreads();
    for (int st = 128; st; st >>= 1) {
        if (tid < st) sm[tid] += sm[tid + st];
        __syncthreads();
    }
    if (tid == 0) {
        const float pos = rowp[idx] * TINV;
        if (mode == 0) g_rowden[idx] = sm[0] + expf(pos - decf(g_rowmax_u[idx]));
        else           g_colden[idx] = sm[0] + expf(pos - decf(g_colmax_u[idx]));
    }
}

// ---------------- kernel 5: final loss + reset max arrays for next replay ----------------
__global__ void loss_kernel(float* __restrict__ out) {
    const int tid = threadIdx.x;  // 512 threads
    __shared__ float sm[B];
    const float pos = g_sim[tid * B + tid] * TINV;
    const float rlog = logf(expf(pos - decf(g_rowmax_u[tid])) / g_rowden[tid] + 1e-20f);
    const float clog = logf(expf(pos - decf(g_colmax_u[tid])) / g_colden[tid] + 1e-20f);
    sm[tid] = -rlog - clog;
    __syncthreads();
    // reset encoded max arrays (0 < encf(any finite float)) for the next replay
    g_rowmax_u[tid] = 0u;
    g_colmax_u[tid] = 0u;
    for (int s = 256; s; s >>= 1) {
        if (tid < s) sm[tid] += sm[tid + s];
        __syncthreads();
    }
    if (tid == 0) out[0] = sm[0] / (2.0f * (float)B);
}

extern "C" void kernel_launch(void* const* d_in, const int* in_sizes, int n_in,
                              void* d_out, int out_size) {
    const float* f1 = (const float*)d_in[0];
    const float* f2 = (const float*)d_in[1];
    const float* bb1 = (const float*)d_in[2];
    const float* bb2 = (const float*)d_in[3];
    float* out = (float*)d_out;

    desc_kernel<<<dim3(B, 2), 512>>>(f1, f2, bb1, bb2);
    simk_kernel<<<dim3(8, 8, 2), 256>>>();
    combineT_kernel<<<dim3(16, 16), 256>>>();
    den_kernel<<<dim3(B, 2), 256>>>();
    loss_kernel<<<1, B>>>(out);
}